// round 6
// baseline (speedup 1.0000x reference)
#include <cuda_runtime.h>
#include <math.h>
#include <stdint.h>

// ---------------- constants ----------------
#define B       32
#define H       21
#define W       180
#define PIX     (H*W)              // 3780
#define FEAT    (192*PIX)          // 725760
#define NSPLIT  360
#define KT      (FEAT/NSPLIT)      // 2016
#define DPI     3.14159265358979323846

// ---------------- scratch (device globals; no runtime allocation) ----------------
__device__ float g_x1[B*64*PIX];
__device__ float g_x2[B*64*PIX];
__device__ float g_x3[B*64*PIX];
__device__ float g_x4[B*64*PIX];
__device__ float g_x5[B*128*PIX];
__device__ float g_x6[B*192*PIX];
__device__ float g_wt_in[64*1*25];      // conv_in packed float2 (oc pairs)
__device__ float g_wf1[204800];         // frag-packed tf32 hi|lo, conv1
__device__ float g_wf2[204800];
__device__ float g_wf3[204800];
__device__ float g_wf4[204800];
__device__ float g_wf5[819200];         // conv5: [mh][...] hi | lo
__device__ float g_part[4*NSPLIT*32*128];
__device__ float g_h1[B*500];
__device__ float g_h2[B*200];
__device__ float g_h3[B*50];
__device__ float g_phi[64];    // phi[3][21] + phi[63]=dy
__device__ float g_trig[720];  // c1,s1,c2,s2 each [180]

// ---------------- tf32 helpers ----------------
__device__ __forceinline__ float tf32_rna(float x) {
    uint32_t u;
    asm("cvt.rna.tf32.f32 %0, %1;" : "=r"(u) : "f"(x));
    return __uint_as_float(u);
}

__device__ __forceinline__ void mma_tf32(float* c, const uint32_t* a, const uint32_t* b) {
    asm("mma.sync.aligned.m16n8k8.row.col.f32.tf32.tf32.f32 "
        "{%0,%1,%2,%3},{%4,%5,%6,%7},{%8,%9},{%0,%1,%2,%3};"
        : "+f"(c[0]), "+f"(c[1]), "+f"(c[2]), "+f"(c[3])
        : "r"(a[0]), "r"(a[1]), "r"(a[2]), "r"(a[3]), "r"(b[0]), "r"(b[1]));
}

// ---------------- init tables ----------------
__global__ void init_tables(float* phi, float* trig) {
    if (blockIdx.x == 0 && threadIdx.x == 0) {
        double beta = 2.28e-11;
        double L = sqrt(51.0 / beta);
        double spi = sqrt(DPI);
        double n0 = sqrt(spi), n1 = sqrt(2.0 * spi), n2 = sqrt(8.0 * spi);
        for (int i = 0; i < 21; i++) {
            double lat = 20.0 - 2.0 * i;
            double y = lat * 110000.0 / L;
            double e = exp(-y * y / 2.0);
            phi[i]      = (float)(e / n0);
            phi[21 + i] = (float)(e * 2.0 * y / n1);
            phi[42 + i] = (float)(e * (4.0 * y * y - 2.0) / n2);
        }
        phi[63] = (float)(2.0 * 110000.0 / L);
        for (int n = 0; n < 180; n++) {
            double t = 2.0 * DPI * (double)n / 180.0;
            trig[n]       = (float)cos(t);
            trig[180 + n] = (float)sin(t);
            trig[360 + n] = (float)cos(2.0 * t);
            trig[540 + n] = (float)sin(2.0 * t);
        }
    }
}

// ---------------- conv_in weight pack: [64][1][25] -> float2 pairs ---------------
__global__ void pack_w(const float* __restrict__ w, float2* __restrict__ wP,
                       int OC, int IC) {
    int OCP = OC >> 1;
    int idx = blockIdx.x * blockDim.x + threadIdx.x;
    int tot = IC * 25 * OCP;
    if (idx >= tot) return;
    int p  = idx % OCP;
    int k  = (idx / OCP) % 25;
    int ic = idx / (OCP * 25);
    float2 v;
    v.x = w[(2 * p    ) * IC * 25 + ic * 25 + k];
    v.y = w[(2 * p + 1) * IC * 25 + ic * 25 + k];
    wP[(ic * 25 + k) * OCP + p] = v;
}

// ---------------- mma weight frag pack (all 5 conv layers, hi/lo tf32) -----------
// Layout per layer: hi[mh][kpos][icgrp][mtile][lane][e] then lo at +Shi.
// e mapping matches m16n8k8 A-fragment: e0(r,c) e1(r+8,c) e2(r,c+4) e3(r+8,c+4),
// r = lane/4, c = lane%4; A[m=oc_local][k=ic_local].
__global__ void pack_frag(const float* __restrict__ w1, const float* __restrict__ w2,
                          const float* __restrict__ w3, const float* __restrict__ w4,
                          const float* __restrict__ w5,
                          float* __restrict__ f1, float* __restrict__ f2,
                          float* __restrict__ f3, float* __restrict__ f4,
                          float* __restrict__ f5)
{
    int idx = blockIdx.x * blockDim.x + threadIdx.x;
    if (idx >= 819200) return;
    const float* w; float* fh; float* fl; int IC; int t; int mh = 0;
    if (idx < 409600) {
        int l = idx / 102400; t = idx % 102400;
        w  = l == 0 ? w1 : l == 1 ? w2 : l == 2 ? w3 : w4;
        fh = l == 0 ? f1 : l == 1 ? f2 : l == 2 ? f3 : f4;
        fl = fh + 102400;
        IC = 64;
    } else {
        t = idx - 409600;
        mh = t / 204800; t %= 204800;
        w = w5; fh = f5; fl = f5 + 409600;
        IC = 128;
    }
    int ICG = IC / 8, P = ICG * 512;
    int kpos = t / P; int r = t % P;
    int icgrp = r / 512; int r2 = r % 512;
    int mtile = r2 / 128; int r3 = r2 % 128;
    int ln = r3 / 4; int e = r3 % 4;
    int row = (ln >> 2) + (e & 1) * 8;
    int col = (ln & 3) + (e >> 1) * 4;
    int oc = mh * 64 + mtile * 16 + row;
    int ic = icgrp * 8 + col;
    float v = w[((size_t)oc * IC + ic) * 25 + kpos];
    float hi = tf32_rna(v);
    size_t dst = (size_t)mh * 25 * P + (size_t)t;
    fh[dst] = hi;
    fl[dst] = tf32_rna(v - hi);
}

// ---------------- conv_in: 1->64 fp32 direct (tiny) ------------------------------
#define FFMA2(d, a, b, c) \
    asm("fma.rn.f32x2 %0, %1, %2, %3;" : "=l"(d) : "l"(a), "l"(b), "l"(c))

template<int IC, int OCP, int YR, int ICC>
__global__ __launch_bounds__(OCP*YR, 3)
void conv5x5_p(const float* __restrict__ in, const float2* __restrict__ wP,
               const float* __restrict__ bias, float* __restrict__ out,
               int outCtot)
{
    constexpr int ROWS = YR + 4;
    constexpr int BT = OCP * YR;
    constexpr int XT = 30;
    extern __shared__ char smraw[];
    float2* sIn = (float2*)smraw;
    float2* sW  = sIn + ICC * ROWS * 36;

    int tid = threadIdx.x;
    int ocp = tid % OCP;
    int yl = tid / OCP;
    int x0 = blockIdx.x * XT, y0 = blockIdx.y * YR, b = blockIdx.z;
    int y = y0 + yl;
    bool valid = (y < H);

    unsigned long long acc[XT];
#pragma unroll
    for (int j = 0; j < XT; j++) acc[j] = 0ull;

#pragma unroll 1
    for (int ic0 = 0; ic0 < IC; ic0 += ICC) {
        __syncthreads();
        for (int i = tid; i < ICC * ROWS * 36; i += BT) {
            int ic = i / (ROWS * 36);
            int r  = (i / 36) % ROWS;
            int xx = i % 36;
            int gy = y0 - 2 + r;
            int gx = x0 - 2 + xx;
            float v = 0.f;
            if (gy >= 0 && gy < H && gx >= 0 && gx < W)
                v = in[((b * IC + ic0 + ic) * H + gy) * W + gx];
            sIn[i] = make_float2(v, v);
        }
        for (int i = tid; i < ICC * 25 * OCP; i += BT)
            sW[i] = wP[ic0 * 25 * OCP + i];
        __syncthreads();

        if (valid) {
#pragma unroll 1
            for (int ic = 0; ic < ICC; ic++) {
#pragma unroll
                for (int kh = 0; kh < 5; kh++) {
                    unsigned long long wp[5];
#pragma unroll
                    for (int kw = 0; kw < 5; kw++)
                        wp[kw] = *reinterpret_cast<const unsigned long long*>(
                            &sW[(ic * 25 + kh * 5 + kw) * OCP + ocp]);
                    const float2* row = &sIn[(ic * ROWS + yl + kh) * 36];
#pragma unroll
                    for (int xs3 = 0; xs3 < 3; xs3++) {
                        const int xs = xs3 * 10;
                        unsigned long long winp[14];
#pragma unroll
                        for (int t = 0; t < 14; t++)
                            winp[t] = *reinterpret_cast<const unsigned long long*>(&row[xs + t]);
#pragma unroll
                        for (int kw = 0; kw < 5; kw++) {
#pragma unroll
                            for (int j = 0; j < 10; j++)
                                FFMA2(acc[xs + j], wp[kw], winp[j + kw], acc[xs + j]);
                        }
                    }
                }
            }
        }
    }

    if (valid) {
        int oc0 = 2 * ocp;
        float bv0 = bias[oc0], bv1 = bias[oc0 + 1];
        float* o0 = out + ((size_t)(b * outCtot + oc0) * H + y) * W + x0;
        float* o1 = o0 + (size_t)H * W;
#pragma unroll
        for (int j = 0; j < XT; j += 2) {
            float2 va = *reinterpret_cast<float2*>(&acc[j]);
            float2 vb = *reinterpret_cast<float2*>(&acc[j + 1]);
            *reinterpret_cast<float2*>(o0 + j) =
                make_float2(fmaxf(va.x + bv0, 0.f), fmaxf(vb.x + bv0, 0.f));
            *reinterpret_cast<float2*>(o1 + j) =
                make_float2(fmaxf(va.y + bv1, 0.f), fmaxf(vb.y + bv1, 0.f));
        }
    }
}

// ---------------- tensor-core conv: 3xTF32 implicit GEMM -------------------------
// Block = one (batch, output row y) [conv5: x mhalf]. Tile M=64 oc x N=192 px.
// K = IC*25 streamed: 16-ic chunks x 25 taps, 8-ic k-steps.
// smem: input hi/lo [16 ic][5 rows][200 x] (ic-stride 1000 == 8 mod 32:
// B-frag lanes (k,n) hit banks 8k+n -> all distinct). Weights in A-frag order.
template<int IC>
__global__ __launch_bounds__(256, 1)
void conv_mma(const float* __restrict__ in,
              const float* __restrict__ pwHi, const float* __restrict__ pwLo,
              const float* __restrict__ bias,
              float* __restrict__ out, int outCtot, int ocOff,
              float* __restrict__ out2, int out2Ctot, int out2Off)
{
    constexpr int ICG = IC / 8;
    constexpr int CHUNKS = IC / 16;
    extern __shared__ float sm[];
    float* sHi = sm;             // 16000
    float* sLo = sm + 16000;     // 16000
    float* sWh = sm + 32000;     // 5120
    float* sWl = sm + 37120;     // 5120

    int tid = threadIdx.x;
    int warpId = tid >> 5;
    int lane = tid & 31;
    int wm = warpId >> 2, wn = warpId & 3;
    int y = blockIdx.x;
    int b = blockIdx.y;
    int mh = blockIdx.z;

    const float* wHi = pwHi + (size_t)mh * 25 * (ICG * 512);
    const float* wLo = pwLo + (size_t)mh * 25 * (ICG * 512);

    float c[2][6][4] = {};

#pragma unroll 1
    for (int ch = 0; ch < CHUNKS; ch++) {
        __syncthreads();
        // input tile: 16 ic x 5 rows x 200 (x index = gx+2), split hi/lo
        for (int i = tid; i < 16000; i += 256) {
            int ic = i / 1000;
            int rr = (i % 1000) / 200;
            int xx = i % 200;
            int gy = y + rr - 2;
            int gx = xx - 2;
            float v = 0.f;
            if (gy >= 0 && gy < H && gx >= 0 && gx < W)
                v = in[((size_t)(b * IC + ch * 16 + ic) * H + gy) * W + gx];
            float hi = tf32_rna(v);
            sHi[i] = hi;
            sLo[i] = tf32_rna(v - hi);
        }
#pragma unroll 1
        for (int kh = 0; kh < 5; kh++) {
            if (kh > 0) __syncthreads();
            // weights for (kh, kw 0..4), icgrps {2ch, 2ch+1}: [kw][g][mtile][lane][e]
            for (int i = tid; i < 5120; i += 256) {
                int kw = i >> 10;
                int r  = i & 1023;
                int g  = r >> 9;
                int off = r & 511;
                size_t src = ((size_t)((kh * 5 + kw) * ICG) + (ch * 2 + g)) * 512 + off;
                sWh[i] = wHi[src];
                sWl[i] = wLo[src];
            }
            __syncthreads();
#pragma unroll 1
            for (int kw = 0; kw < 5; kw++) {
#pragma unroll
                for (int ks = 0; ks < 2; ks++) {
                    uint32_t ah[2][4], al[2][4];
#pragma unroll
                    for (int mt = 0; mt < 2; mt++) {
                        int mtile = wm * 2 + mt;
                        int base = ((kw * 2 + ks) * 4 + mtile) * 128 + lane * 4;
                        *(float4*)ah[mt] = *(const float4*)&sWh[base];
                        *(float4*)al[mt] = *(const float4*)&sWl[base];
                    }
                    int krow = lane & 3, nId = lane >> 2;
                    int bbase = (ks * 8 + krow) * 1000 + kh * 200 + wn * 48 + nId + kw;
#pragma unroll
                    for (int nt = 0; nt < 6; nt++) {
                        uint32_t bh[2], bl[2];
                        int bi = bbase + nt * 8;
                        bh[0] = __float_as_uint(sHi[bi]);
                        bh[1] = __float_as_uint(sHi[bi + 4000]);
                        bl[0] = __float_as_uint(sLo[bi]);
                        bl[1] = __float_as_uint(sLo[bi + 4000]);
#pragma unroll
                        for (int mt = 0; mt < 2; mt++) {
                            mma_tf32(c[mt][nt], ah[mt], bh);
                            mma_tf32(c[mt][nt], ah[mt], bl);
                            mma_tf32(c[mt][nt], al[mt], bh);
                        }
                    }
                }
            }
        }
    }

    // epilogue: bias + relu + store (x<180), optional concat dual-write
    int ocL = mh * 64 + wm * 32;
#pragma unroll
    for (int mt = 0; mt < 2; mt++) {
        int ocRow = ocL + mt * 16 + (lane >> 2);
        float bv0 = bias[ocRow], bv8 = bias[ocRow + 8];
#pragma unroll
        for (int nt = 0; nt < 6; nt++) {
            int x = wn * 48 + nt * 8 + (lane & 3) * 2;
            if (x < W) {
                float2 v0 = make_float2(fmaxf(c[mt][nt][0] + bv0, 0.f),
                                        fmaxf(c[mt][nt][1] + bv0, 0.f));
                float2 v1 = make_float2(fmaxf(c[mt][nt][2] + bv8, 0.f),
                                        fmaxf(c[mt][nt][3] + bv8, 0.f));
                size_t o0 = ((size_t)(b * outCtot + ocOff + ocRow) * H + y) * W + x;
                size_t o1 = o0 + (size_t)8 * H * W;
                *(float2*)&out[o0] = v0;
                *(float2*)&out[o1] = v1;
                if (out2) {
                    size_t q0 = ((size_t)(b * out2Ctot + out2Off + ocRow) * H + y) * W + x;
                    size_t q1 = q0 + (size_t)8 * H * W;
                    *(float2*)&out2[q0] = v0;
                    *(float2*)&out2[q1] = v1;
                }
            }
        }
    }
}

// ---------------- Hermite residual along lat, in place ---------------------------
__global__ void filter_lat(float* __restrict__ x, const float* __restrict__ phi)
{
    int idx = blockIdx.x * blockDim.x + threadIdx.x;
    if (idx >= B * 192 * W) return;
    int xi = idx % W;
    int c  = (idx / W) % 192;
    int b  = idx / (W * 192);
    float* base = x + (size_t)((b * 192 + c) * H) * W + xi;
    float v[21];
#pragma unroll
    for (int y = 0; y < 21; y++) v[y] = base[y * W];
    float dy = phi[63];
    float u0 = 0.f, u1 = 0.f, u2 = 0.f;
#pragma unroll
    for (int y = 0; y < 21; y++) {
        u0 += v[y] * phi[y];
        u1 += v[y] * phi[21 + y];
        u2 += v[y] * phi[42 + y];
    }
    u0 *= dy; u1 *= dy; u2 *= dy;
#pragma unroll
    for (int y = 0; y < 21; y++)
        base[y * W] = v[y] - (u0 * phi[y] + u1 * phi[21 + y] + u2 * phi[42 + y]);
}

// ---------------- Fourier low-mode residual along lon (k=0,1,2), in place --------
__global__ void filter_lon(float* __restrict__ x, const float* __restrict__ trig)
{
    int gw = (blockIdx.x * blockDim.x + threadIdx.x) >> 5;
    int lane = threadIdx.x & 31;
    if (gw >= B * 192 * H) return;
    float* row = x + (size_t)gw * W;
    const float* c1 = trig, *s1 = trig + 180, *c2 = trig + 360, *s2 = trig + 540;
    float v[6];
    float q0 = 0.f, q1 = 0.f, q2 = 0.f, q3 = 0.f, q4 = 0.f;
#pragma unroll
    for (int t = 0; t < 6; t++) {
        int n = t * 32 + lane;
        if (n < W) {
            float xv = row[n];
            v[t] = xv;
            q0 += xv;
            q1 += xv * c1[n];
            q2 += xv * s1[n];
            q3 += xv * c2[n];
            q4 += xv * s2[n];
        }
    }
#pragma unroll
    for (int o = 16; o; o >>= 1) {
        q0 += __shfl_xor_sync(0xffffffffu, q0, o);
        q1 += __shfl_xor_sync(0xffffffffu, q1, o);
        q2 += __shfl_xor_sync(0xffffffffu, q2, o);
        q3 += __shfl_xor_sync(0xffffffffu, q3, o);
        q4 += __shfl_xor_sync(0xffffffffu, q4, o);
    }
    const float inv = 1.f / 180.f, inv2 = 2.f / 180.f;
#pragma unroll
    for (int t = 0; t < 6; t++) {
        int n = t * 32 + lane;
        if (n < W)
            row[n] = v[t] - q0 * inv
                   - inv2 * (q1 * c1[n] + q2 * s1[n] + q3 * c2[n] + q4 * s2[n]);
    }
}

// ---------------- FC1: [32 x 725760] x [500 x 725760]^T, split-K -----------------
__global__ __launch_bounds__(128)
void fc1_partial(const float* __restrict__ act, const float* __restrict__ w,
                 float* __restrict__ part)
{
    __shared__ __align__(16) float As[32 * 36];
    __shared__ __align__(16) float Ws[32 * 132];
    int tid = threadIdx.x;
    int ks = blockIdx.x, jg = blockIdx.y;
    int kb = ks * KT;
    int jg0 = jg * 128;
    int bq = tid & 7, jq = tid >> 3;
    int b0 = bq * 4, j0 = jq * 8;

    float acc[4][8];
#pragma unroll
    for (int i = 0; i < 4; i++)
#pragma unroll
        for (int j = 0; j < 8; j++) acc[i][j] = 0.f;

#pragma unroll 1
    for (int kk = 0; kk < KT; kk += 32) {
        __syncthreads();
#pragma unroll
        for (int r = 0; r < 8; r++) {
            int i = tid + r * 128;
            int bb = i >> 5, k = i & 31;
            As[k * 36 + bb] = act[bb * FEAT + kb + kk + k];
        }
#pragma unroll
        for (int r = 0; r < 32; r++) {
            int i = tid + r * 128;
            int j = i >> 5, k = i & 31;
            int jglob = jg0 + j;
            Ws[k * 132 + j] = (jglob < 500) ? w[(size_t)jglob * FEAT + kb + kk + k] : 0.f;
        }
        __syncthreads();
#pragma unroll 4
        for (int k = 0; k < 32; k++) {
            float4 a  = *reinterpret_cast<const float4*>(&As[k * 36 + b0]);
            float4 w0 = *reinterpret_cast<const float4*>(&Ws[k * 132 + j0]);
            float4 w1 = *reinterpret_cast<const float4*>(&Ws[k * 132 + j0 + 4]);
            float av[4] = {a.x, a.y, a.z, a.w};
            float wv[8] = {w0.x, w0.y, w0.z, w0.w, w1.x, w1.y, w1.z, w1.w};
#pragma unroll
            for (int bb = 0; bb < 4; bb++)
#pragma unroll
                for (int jj = 0; jj < 8; jj++)
                    acc[bb][jj] = fmaf(av[bb], wv[jj], acc[bb][jj]);
        }
    }
#pragma unroll
    for (int bb = 0; bb < 4; bb++)
#pragma unroll
        for (int jj = 0; jj < 8; jj++)
            part[((size_t)(jg * NSPLIT + ks) * 32 + (b0 + bb)) * 128 + j0 + jj] = acc[bb][jj];
}

__global__ void fc1_reduce(const float* __restrict__ part, const float* __restrict__ bias,
                           float* __restrict__ h1)
{
    int idx = blockIdx.x * blockDim.x + threadIdx.x;
    if (idx >= 32 * 512) return;
    int jl = idx & 127;
    int jg = (idx >> 7) & 3;
    int b  = idx >> 9;
    int j = jg * 128 + jl;
    if (j >= 500) return;
    float s = bias[j];
    for (int ks = 0; ks < NSPLIT; ks++)
        s += part[((size_t)(jg * NSPLIT + ks) * 32 + b) * 128 + jl];
    h1[b * 500 + j] = s;    // pre-relu; relu applied when FC2 loads
}

// ---------------- small FC layers ----------------
__global__ void fc_small(const float* __restrict__ in, const float* __restrict__ w,
                         const float* __restrict__ bias, float* __restrict__ out,
                         int N, int K, int reluIn, int reluOut)
{
    int idx = blockIdx.x * blockDim.x + threadIdx.x;
    if (idx >= 32 * N) return;
    int b = idx / N, n = idx % N;
    float s = bias[n];
    const float* ip = in + b * K;
    const float* wp = w + n * K;
    for (int k = 0; k < K; k++) {
        float a = ip[k];
        if (reluIn) a = fmaxf(a, 0.f);
        s = fmaf(a, wp[k], s);
    }
    if (reluOut) s = fmaxf(s, 0.f);
    out[idx] = s;
}

// ---------------- host launcher ----------------
extern "C" void kernel_launch(void* const* d_in, const int* in_sizes, int n_in,
                              void* d_out, int out_size)
{
    const float* x     = (const float*)d_in[0];
    const float* w_in  = (const float*)d_in[1];
    const float* b_in  = (const float*)d_in[2];
    const float* w1    = (const float*)d_in[3];
    const float* b1    = (const float*)d_in[4];
    const float* w2    = (const float*)d_in[5];
    const float* b2    = (const float*)d_in[6];
    const float* w3    = (const float*)d_in[7];
    const float* b3    = (const float*)d_in[8];
    const float* w4    = (const float*)d_in[9];
    const float* b4    = (const float*)d_in[10];
    const float* w5    = (const float*)d_in[11];
    const float* b5    = (const float*)d_in[12];
    const float* wfc1  = (const float*)d_in[13];
    const float* bfc1  = (const float*)d_in[14];
    const float* wfc2  = (const float*)d_in[15];
    const float* bfc2  = (const float*)d_in[16];
    const float* wfc3  = (const float*)d_in[17];
    const float* bfc3  = (const float*)d_in[18];
    const float* wfc4  = (const float*)d_in[19];
    const float* bfc4  = (const float*)d_in[20];
    float* out = (float*)d_out;

    float *x1, *x2, *x3, *x4, *x5, *x6;
    float *wpin, *wf1, *wf2, *wf3, *wf4, *wf5;
    float *part, *h1, *h2, *h3, *phi, *trig;
    cudaGetSymbolAddress((void**)&x1, g_x1);
    cudaGetSymbolAddress((void**)&x2, g_x2);
    cudaGetSymbolAddress((void**)&x3, g_x3);
    cudaGetSymbolAddress((void**)&x4, g_x4);
    cudaGetSymbolAddress((void**)&x5, g_x5);
    cudaGetSymbolAddress((void**)&x6, g_x6);
    cudaGetSymbolAddress((void**)&wpin, g_wt_in);
    cudaGetSymbolAddress((void**)&wf1, g_wf1);
    cudaGetSymbolAddress((void**)&wf2, g_wf2);
    cudaGetSymbolAddress((void**)&wf3, g_wf3);
    cudaGetSymbolAddress((void**)&wf4, g_wf4);
    cudaGetSymbolAddress((void**)&wf5, g_wf5);
    cudaGetSymbolAddress((void**)&part, g_part);
    cudaGetSymbolAddress((void**)&h1, g_h1);
    cudaGetSymbolAddress((void**)&h2, g_h2);
    cudaGetSymbolAddress((void**)&h3, g_h3);
    cudaGetSymbolAddress((void**)&phi, g_phi);
    cudaGetSymbolAddress((void**)&trig, g_trig);

    const int smem_in = (1 * 8 * 36 + 1 * 25 * 32) * 8;       //  8704
    const int smem_c  = 42240 * 4;                            // 168960
    cudaFuncSetAttribute(conv_mma<64>,
                         cudaFuncAttributeMaxDynamicSharedMemorySize, smem_c);
    cudaFuncSetAttribute(conv_mma<128>,
                         cudaFuncAttributeMaxDynamicSharedMemorySize, smem_c);

    // prologue: L0 tables, L1 conv_in pack, L2 frag pack
    init_tables<<<1, 1>>>(phi, trig);
    pack_w<<<(1 * 25 * 32 + 255) / 256, 256>>>(w_in, (float2*)wpin, 64, 1);
    pack_frag<<<(819200 + 255) / 256, 256>>>(w1, w2, w3, w4, w5,
                                             wf1, wf2, wf3, wf4, wf5);

    // L3: conv_in (fp32, tiny)
    conv5x5_p<1, 32, 4, 1><<<dim3(6, 6, B), 128, smem_in>>>(x, (float2*)wpin, b_in, x1, 64);

    // L4-L8: tensor-core convs (3xTF32); concat fused via dual-write
    dim3 gm(21, B, 1);
    conv_mma<64><<<gm, 256, smem_c>>>(x1, wf1, wf1 + 102400, b1, x2, 64, 0,
                                      x6, 192, 128);   // x2 also -> x6[128:192]
    conv_mma<64><<<gm, 256, smem_c>>>(x2, wf2, wf2 + 102400, b2, x3, 64, 0,
                                      x5, 128, 64);    // x3 also -> x5[64:128]
    conv_mma<64><<<gm, 256, smem_c>>>(x3, wf3, wf3 + 102400, b3, x4, 64, 0,
                                      nullptr, 0, 0);
    conv_mma<64><<<gm, 256, smem_c>>>(x4, wf4, wf4 + 102400, b4, x5, 128, 0,
                                      nullptr, 0, 0);  // x5[0:64]
    conv_mma<128><<<dim3(21, B, 2), 256, smem_c>>>(x5, wf5, wf5 + 409600, b5, x6, 192, 0,
                                                   nullptr, 0, 0);  // x6[0:128]

    // residual filters (closed-form projections; no FFT)
    filter_lat<<<(B * 192 * W + 255) / 256, 256>>>(x6, phi);
    filter_lon<<<(B * 192 * H * 32 + 255) / 256, 256>>>(x6, trig);

    // FC stack
    fc1_partial<<<dim3(NSPLIT, 4), 128>>>(x6, wfc1, part);
    fc1_reduce<<<64, 256>>>(part, bfc1, h1);
    fc_small<<<(32 * 200 + 255) / 256, 256>>>(h1, wfc2, bfc2, h2, 200, 500, 1, 1);
    fc_small<<<(32 * 50 + 255) / 256, 256>>>(h2, wfc3, bfc3, h3, 50, 200, 0, 1);
    fc_small<<<1, 64>>>(h3, wfc4, bfc4, out, 2, 50, 0, 0);
}

// round 7
// speedup vs baseline: 1.2013x; 1.2013x over previous
#include <cuda_runtime.h>
#include <math.h>
#include <stdint.h>

// ---------------- constants ----------------
#define B       32
#define H       21
#define W       180
#define PIX     (H*W)              // 3780
#define FEAT    (192*PIX)          // 725760
#define NSPLIT  360
#define KT      (FEAT/NSPLIT)      // 2016
#define DPI     3.14159265358979323846

// ---------------- scratch (device globals; no runtime allocation) ----------------
__device__ float g_x1[B*64*PIX];
__device__ float g_x2[B*64*PIX];
__device__ float g_x3[B*64*PIX];
__device__ float g_x4[B*64*PIX];
__device__ float g_x5[B*128*PIX];
__device__ float g_x6[B*192*PIX];
__device__ float g_wt_in[64*1*25];      // conv_in packed float2 (oc pairs)
__device__ float g_wf1[204800];         // frag-packed tf32 hi|lo, conv1
__device__ float g_wf2[204800];
__device__ float g_wf3[204800];
__device__ float g_wf4[204800];
__device__ float g_wf5[819200];         // conv5: [mh][...] hi | lo
__device__ float g_part[4*NSPLIT*32*128];
__device__ float g_h1[B*500];
__device__ float g_h2[B*200];
__device__ float g_h3[B*50];
__device__ float g_phi[64];    // phi[3][21] + phi[63]=dy
__device__ float g_trig[720];  // c1,s1,c2,s2 each [180]

// ---------------- tf32 helpers ----------------
__device__ __forceinline__ float tf32_rna(float x) {
    uint32_t u;
    asm("cvt.rna.tf32.f32 %0, %1;" : "=r"(u) : "f"(x));
    return __uint_as_float(u);
}

__device__ __forceinline__ void mma_tf32(float* c, const uint32_t* a, const uint32_t* b) {
    asm("mma.sync.aligned.m16n8k8.row.col.f32.tf32.tf32.f32 "
        "{%0,%1,%2,%3},{%4,%5,%6,%7},{%8,%9},{%0,%1,%2,%3};"
        : "+f"(c[0]), "+f"(c[1]), "+f"(c[2]), "+f"(c[3])
        : "r"(a[0]), "r"(a[1]), "r"(a[2]), "r"(a[3]), "r"(b[0]), "r"(b[1]));
}

// ---------------- init tables ----------------
__global__ void init_tables(float* phi, float* trig) {
    if (blockIdx.x == 0 && threadIdx.x == 0) {
        double beta = 2.28e-11;
        double L = sqrt(51.0 / beta);
        double spi = sqrt(DPI);
        double n0 = sqrt(spi), n1 = sqrt(2.0 * spi), n2 = sqrt(8.0 * spi);
        for (int i = 0; i < 21; i++) {
            double lat = 20.0 - 2.0 * i;
            double y = lat * 110000.0 / L;
            double e = exp(-y * y / 2.0);
            phi[i]      = (float)(e / n0);
            phi[21 + i] = (float)(e * 2.0 * y / n1);
            phi[42 + i] = (float)(e * (4.0 * y * y - 2.0) / n2);
        }
        phi[63] = (float)(2.0 * 110000.0 / L);
        for (int n = 0; n < 180; n++) {
            double t = 2.0 * DPI * (double)n / 180.0;
            trig[n]       = (float)cos(t);
            trig[180 + n] = (float)sin(t);
            trig[360 + n] = (float)cos(2.0 * t);
            trig[540 + n] = (float)sin(2.0 * t);
        }
    }
}

// ---------------- conv_in weight pack: [64][1][25] -> float2 pairs ---------------
__global__ void pack_w(const float* __restrict__ w, float2* __restrict__ wP,
                       int OC, int IC) {
    int OCP = OC >> 1;
    int idx = blockIdx.x * blockDim.x + threadIdx.x;
    int tot = IC * 25 * OCP;
    if (idx >= tot) return;
    int p  = idx % OCP;
    int k  = (idx / OCP) % 25;
    int ic = idx / (OCP * 25);
    float2 v;
    v.x = w[(2 * p    ) * IC * 25 + ic * 25 + k];
    v.y = w[(2 * p + 1) * IC * 25 + ic * 25 + k];
    wP[(ic * 25 + k) * OCP + p] = v;
}

// ---------------- mma weight frag pack (hi/lo tf32), layout unchanged ------------
// hi[mh][kpos][icgrp][mtile][lane][e], lo at +Shi. e matches m16n8k8 A-fragment.
__global__ void pack_frag(const float* __restrict__ w1, const float* __restrict__ w2,
                          const float* __restrict__ w3, const float* __restrict__ w4,
                          const float* __restrict__ w5,
                          float* __restrict__ f1, float* __restrict__ f2,
                          float* __restrict__ f3, float* __restrict__ f4,
                          float* __restrict__ f5)
{
    int idx = blockIdx.x * blockDim.x + threadIdx.x;
    if (idx >= 819200) return;
    const float* w; float* fh; float* fl; int IC; int t; int mh = 0;
    if (idx < 409600) {
        int l = idx / 102400; t = idx % 102400;
        w  = l == 0 ? w1 : l == 1 ? w2 : l == 2 ? w3 : w4;
        fh = l == 0 ? f1 : l == 1 ? f2 : l == 2 ? f3 : f4;
        fl = fh + 102400;
        IC = 64;
    } else {
        t = idx - 409600;
        mh = t / 204800; t %= 204800;
        w = w5; fh = f5; fl = f5 + 409600;
        IC = 128;
    }
    int ICG = IC / 8, P = ICG * 512;
    int kpos = t / P; int r = t % P;
    int icgrp = r / 512; int r2 = r % 512;
    int mtile = r2 / 128; int r3 = r2 % 128;
    int ln = r3 / 4; int e = r3 % 4;
    int row = (ln >> 2) + (e & 1) * 8;
    int col = (ln & 3) + (e >> 1) * 4;
    int oc = mh * 64 + mtile * 16 + row;
    int ic = icgrp * 8 + col;
    float v = w[((size_t)oc * IC + ic) * 25 + kpos];
    float hi = tf32_rna(v);
    size_t dst = (size_t)mh * 25 * P + (size_t)t;
    fh[dst] = hi;
    fl[dst] = tf32_rna(v - hi);
}

// ---------------- conv_in: 1->64 fp32 direct (tiny) ------------------------------
#define FFMA2(d, a, b, c) \
    asm("fma.rn.f32x2 %0, %1, %2, %3;" : "=l"(d) : "l"(a), "l"(b), "l"(c))

template<int IC, int OCP, int YR, int ICC>
__global__ __launch_bounds__(OCP*YR, 3)
void conv5x5_p(const float* __restrict__ in, const float2* __restrict__ wP,
               const float* __restrict__ bias, float* __restrict__ out,
               int outCtot)
{
    constexpr int ROWS = YR + 4;
    constexpr int BT = OCP * YR;
    constexpr int XT = 30;
    extern __shared__ char smraw[];
    float2* sIn = (float2*)smraw;
    float2* sW  = sIn + ICC * ROWS * 36;

    int tid = threadIdx.x;
    int ocp = tid % OCP;
    int yl = tid / OCP;
    int x0 = blockIdx.x * XT, y0 = blockIdx.y * YR, b = blockIdx.z;
    int y = y0 + yl;
    bool valid = (y < H);

    unsigned long long acc[XT];
#pragma unroll
    for (int j = 0; j < XT; j++) acc[j] = 0ull;

#pragma unroll 1
    for (int ic0 = 0; ic0 < IC; ic0 += ICC) {
        __syncthreads();
        for (int i = tid; i < ICC * ROWS * 36; i += BT) {
            int ic = i / (ROWS * 36);
            int r  = (i / 36) % ROWS;
            int xx = i % 36;
            int gy = y0 - 2 + r;
            int gx = x0 - 2 + xx;
            float v = 0.f;
            if (gy >= 0 && gy < H && gx >= 0 && gx < W)
                v = in[((b * IC + ic0 + ic) * H + gy) * W + gx];
            sIn[i] = make_float2(v, v);
        }
        for (int i = tid; i < ICC * 25 * OCP; i += BT)
            sW[i] = wP[ic0 * 25 * OCP + i];
        __syncthreads();

        if (valid) {
#pragma unroll 1
            for (int ic = 0; ic < ICC; ic++) {
#pragma unroll
                for (int kh = 0; kh < 5; kh++) {
                    unsigned long long wp[5];
#pragma unroll
                    for (int kw = 0; kw < 5; kw++)
                        wp[kw] = *reinterpret_cast<const unsigned long long*>(
                            &sW[(ic * 25 + kh * 5 + kw) * OCP + ocp]);
                    const float2* row = &sIn[(ic * ROWS + yl + kh) * 36];
#pragma unroll
                    for (int xs3 = 0; xs3 < 3; xs3++) {
                        const int xs = xs3 * 10;
                        unsigned long long winp[14];
#pragma unroll
                        for (int t = 0; t < 14; t++)
                            winp[t] = *reinterpret_cast<const unsigned long long*>(&row[xs + t]);
#pragma unroll
                        for (int kw = 0; kw < 5; kw++) {
#pragma unroll
                            for (int j = 0; j < 10; j++)
                                FFMA2(acc[xs + j], wp[kw], winp[j + kw], acc[xs + j]);
                        }
                    }
                }
            }
        }
    }

    if (valid) {
        int oc0 = 2 * ocp;
        float bv0 = bias[oc0], bv1 = bias[oc0 + 1];
        float* o0 = out + ((size_t)(b * outCtot + oc0) * H + y) * W + x0;
        float* o1 = o0 + (size_t)H * W;
#pragma unroll
        for (int j = 0; j < XT; j += 2) {
            float2 va = *reinterpret_cast<float2*>(&acc[j]);
            float2 vb = *reinterpret_cast<float2*>(&acc[j + 1]);
            *reinterpret_cast<float2*>(o0 + j) =
                make_float2(fmaxf(va.x + bv0, 0.f), fmaxf(vb.x + bv0, 0.f));
            *reinterpret_cast<float2*>(o1 + j) =
                make_float2(fmaxf(va.y + bv1, 0.f), fmaxf(vb.y + bv1, 0.f));
        }
    }
}

// ---------------- tensor-core conv: 3xTF32 implicit GEMM, N=96 tiles -------------
// Block = (xhalf, y row, batch) [conv5: mh via blockIdx.x>>1]. Tile M=64 x N=96.
// smem ~105KB -> 2 CTAs/SM (16 warps) for latency hiding across sync phases.
// Input smem: 16 ic x 5 rows x 104 cols, hi/lo split; ic-stride 520 == 8 mod 32
// -> B-frag lanes (k,n) hit banks 8k+n, all distinct. Weights in A-frag order.
template<int IC>
__global__ __launch_bounds__(256, 2)
void conv_mma(const float* __restrict__ in,
              const float* __restrict__ pwHi, const float* __restrict__ pwLo,
              const float* __restrict__ bias,
              float* __restrict__ out, int outCtot, int ocOff,
              float* __restrict__ out2, int out2Ctot, int out2Off)
{
    constexpr int ICG = IC / 8;
    constexpr int CHUNKS = IC / 16;
    constexpr int XS = 520;    // ic stride (floats)
    constexpr int RS = 104;    // row stride
    extern __shared__ float sm[];
    float* sHi = sm;           // 8320
    float* sLo = sm + 8320;    // 8320
    float* sWh = sm + 16640;   // 5120
    float* sWl = sm + 21760;   // 5120  (total 26880 floats = 105KB)

    int tid = threadIdx.x;
    int warpId = tid >> 5;
    int lane = tid & 31;
    int wm = warpId >> 2, wn = warpId & 3;
    int xh = blockIdx.x & 1;
    int mh = blockIdx.x >> 1;
    int y = blockIdx.y;
    int b = blockIdx.z;
    int x0 = xh * 96;

    const float* wHi = pwHi + (size_t)mh * 25 * (ICG * 512);
    const float* wLo = pwLo + (size_t)mh * 25 * (ICG * 512);

    float c[2][3][4] = {};

    int licq = tid >> 4;       // 0..15: ic within chunk
    int lx   = tid & 15;

#pragma unroll 1
    for (int ch = 0; ch < CHUNKS; ch++) {
        __syncthreads();
        // input tile: structured, additive indexing, coalesced 16-wide
        {
            const float* inc = in + (size_t)(b * IC + ch * 16 + licq) * H * W;
            float* dHi = sHi + licq * XS;
            float* dLo = sLo + licq * XS;
#pragma unroll
            for (int r = 0; r < 5; r++) {
                int gy = y + r - 2;
                bool okY = (gy >= 0 && gy < H);
                const float* rp = inc + gy * W + x0 - 2;
#pragma unroll
                for (int xx = lx; xx < 104; xx += 16) {
                    int gx = x0 - 2 + xx;
                    float v = (okY && gx >= 0 && gx < W) ? rp[xx] : 0.f;
                    float hi = tf32_rna(v);
                    dHi[r * RS + xx] = hi;
                    dLo[r * RS + xx] = tf32_rna(v - hi);
                }
            }
        }
#pragma unroll 1
        for (int kh = 0; kh < 5; kh++) {
            __syncthreads();
            // weights (kh, kw 0..4), icgrps {2ch,2ch+1}: [kw][g][mtile][lane][e]
            for (int i = tid; i < 5120; i += 256) {
                int kw = i >> 10;
                int g  = (i >> 9) & 1;
                int off = i & 511;
                size_t src = ((size_t)((kh * 5 + kw) * ICG) + (ch * 2 + g)) * 512 + off;
                sWh[i] = wHi[src];
                sWl[i] = wLo[src];
            }
            __syncthreads();
#pragma unroll 1
            for (int kw = 0; kw < 5; kw++) {
#pragma unroll
                for (int ks = 0; ks < 2; ks++) {
                    uint32_t ah[2][4], al[2][4];
#pragma unroll
                    for (int mt = 0; mt < 2; mt++) {
                        int mtile = wm * 2 + mt;
                        int base = ((kw * 2 + ks) * 4 + mtile) * 128 + lane * 4;
                        *(float4*)ah[mt] = *(const float4*)&sWh[base];
                        *(float4*)al[mt] = *(const float4*)&sWl[base];
                    }
                    int krow = lane & 3, nId = lane >> 2;
                    int bbase = (ks * 8 + krow) * XS + kh * RS + wn * 24 + nId + kw;
#pragma unroll
                    for (int nt = 0; nt < 3; nt++) {
                        uint32_t bh[2], bl[2];
                        int bi = bbase + nt * 8;
                        bh[0] = __float_as_uint(sHi[bi]);
                        bh[1] = __float_as_uint(sHi[bi + 4 * XS]);
                        bl[0] = __float_as_uint(sLo[bi]);
                        bl[1] = __float_as_uint(sLo[bi + 4 * XS]);
#pragma unroll
                        for (int mt = 0; mt < 2; mt++) {
                            mma_tf32(c[mt][nt], ah[mt], bh);
                            mma_tf32(c[mt][nt], ah[mt], bl);
                            mma_tf32(c[mt][nt], al[mt], bh);
                        }
                    }
                }
            }
        }
    }

    // epilogue: bias + relu + store, optional concat dual-write
    int ocL = mh * 64 + wm * 32;
#pragma unroll
    for (int mt = 0; mt < 2; mt++) {
        int ocRow = ocL + mt * 16 + (lane >> 2);
        float bv0 = bias[ocRow], bv8 = bias[ocRow + 8];
#pragma unroll
        for (int nt = 0; nt < 3; nt++) {
            int x = x0 + wn * 24 + nt * 8 + (lane & 3) * 2;
            if (x < W) {
                float2 v0 = make_float2(fmaxf(c[mt][nt][0] + bv0, 0.f),
                                        fmaxf(c[mt][nt][1] + bv0, 0.f));
                float2 v1 = make_float2(fmaxf(c[mt][nt][2] + bv8, 0.f),
                                        fmaxf(c[mt][nt][3] + bv8, 0.f));
                size_t o0 = ((size_t)(b * outCtot + ocOff + ocRow) * H + y) * W + x;
                size_t o1 = o0 + (size_t)8 * H * W;
                *(float2*)&out[o0] = v0;
                *(float2*)&out[o1] = v1;
                if (out2) {
                    size_t q0 = ((size_t)(b * out2Ctot + out2Off + ocRow) * H + y) * W + x;
                    size_t q1 = q0 + (size_t)8 * H * W;
                    *(float2*)&out2[q0] = v0;
                    *(float2*)&out2[q1] = v1;
                }
            }
        }
    }
}

// ---------------- Hermite residual along lat, in place ---------------------------
__global__ void filter_lat(float* __restrict__ x, const float* __restrict__ phi)
{
    int idx = blockIdx.x * blockDim.x + threadIdx.x;
    if (idx >= B * 192 * W) return;
    int xi = idx % W;
    int c  = (idx / W) % 192;
    int b  = idx / (W * 192);
    float* base = x + (size_t)((b * 192 + c) * H) * W + xi;
    float v[21];
#pragma unroll
    for (int y = 0; y < 21; y++) v[y] = base[y * W];
    float dy = phi[63];
    float u0 = 0.f, u1 = 0.f, u2 = 0.f;
#pragma unroll
    for (int y = 0; y < 21; y++) {
        u0 += v[y] * phi[y];
        u1 += v[y] * phi[21 + y];
        u2 += v[y] * phi[42 + y];
    }
    u0 *= dy; u1 *= dy; u2 *= dy;
#pragma unroll
    for (int y = 0; y < 21; y++)
        base[y * W] = v[y] - (u0 * phi[y] + u1 * phi[21 + y] + u2 * phi[42 + y]);
}

// ---------------- Fourier low-mode residual along lon (k=0,1,2), in place --------
__global__ void filter_lon(float* __restrict__ x, const float* __restrict__ trig)
{
    int gw = (blockIdx.x * blockDim.x + threadIdx.x) >> 5;
    int lane = threadIdx.x & 31;
    if (gw >= B * 192 * H) return;
    float* row = x + (size_t)gw * W;
    const float* c1 = trig, *s1 = trig + 180, *c2 = trig + 360, *s2 = trig + 540;
    float v[6];
    float q0 = 0.f, q1 = 0.f, q2 = 0.f, q3 = 0.f, q4 = 0.f;
#pragma unroll
    for (int t = 0; t < 6; t++) {
        int n = t * 32 + lane;
        if (n < W) {
            float xv = row[n];
            v[t] = xv;
            q0 += xv;
            q1 += xv * c1[n];
            q2 += xv * s1[n];
            q3 += xv * c2[n];
            q4 += xv * s2[n];
        }
    }
#pragma unroll
    for (int o = 16; o; o >>= 1) {
        q0 += __shfl_xor_sync(0xffffffffu, q0, o);
        q1 += __shfl_xor_sync(0xffffffffu, q1, o);
        q2 += __shfl_xor_sync(0xffffffffu, q2, o);
        q3 += __shfl_xor_sync(0xffffffffu, q3, o);
        q4 += __shfl_xor_sync(0xffffffffu, q4, o);
    }
    const float inv = 1.f / 180.f, inv2 = 2.f / 180.f;
#pragma unroll
    for (int t = 0; t < 6; t++) {
        int n = t * 32 + lane;
        if (n < W)
            row[n] = v[t] - q0 * inv
                   - inv2 * (q1 * c1[n] + q2 * s1[n] + q3 * c2[n] + q4 * s2[n]);
    }
}

// ---------------- FC1: [32 x 725760] x [500 x 725760]^T, split-K -----------------
__global__ __launch_bounds__(128)
void fc1_partial(const float* __restrict__ act, const float* __restrict__ w,
                 float* __restrict__ part)
{
    __shared__ __align__(16) float As[32 * 36];
    __shared__ __align__(16) float Ws[32 * 132];
    int tid = threadIdx.x;
    int ks = blockIdx.x, jg = blockIdx.y;
    int kb = ks * KT;
    int jg0 = jg * 128;
    int bq = tid & 7, jq = tid >> 3;
    int b0 = bq * 4, j0 = jq * 8;

    float acc[4][8];
#pragma unroll
    for (int i = 0; i < 4; i++)
#pragma unroll
        for (int j = 0; j < 8; j++) acc[i][j] = 0.f;

#pragma unroll 1
    for (int kk = 0; kk < KT; kk += 32) {
        __syncthreads();
#pragma unroll
        for (int r = 0; r < 8; r++) {
            int i = tid + r * 128;
            int bb = i >> 5, k = i & 31;
            As[k * 36 + bb] = act[bb * FEAT + kb + kk + k];
        }
#pragma unroll
        for (int r = 0; r < 32; r++) {
            int i = tid + r * 128;
            int j = i >> 5, k = i & 31;
            int jglob = jg0 + j;
            Ws[k * 132 + j] = (jglob < 500) ? w[(size_t)jglob * FEAT + kb + kk + k] : 0.f;
        }
        __syncthreads();
#pragma unroll 4
        for (int k = 0; k < 32; k++) {
            float4 a  = *reinterpret_cast<const float4*>(&As[k * 36 + b0]);
            float4 w0 = *reinterpret_cast<const float4*>(&Ws[k * 132 + j0]);
            float4 w1 = *reinterpret_cast<const float4*>(&Ws[k * 132 + j0 + 4]);
            float av[4] = {a.x, a.y, a.z, a.w};
            float wv[8] = {w0.x, w0.y, w0.z, w0.w, w1.x, w1.y, w1.z, w1.w};
#pragma unroll
            for (int bb = 0; bb < 4; bb++)
#pragma unroll
                for (int jj = 0; jj < 8; jj++)
                    acc[bb][jj] = fmaf(av[bb], wv[jj], acc[bb][jj]);
        }
    }
#pragma unroll
    for (int bb = 0; bb < 4; bb++)
#pragma unroll
        for (int jj = 0; jj < 8; jj++)
            part[((size_t)(jg * NSPLIT + ks) * 32 + (b0 + bb)) * 128 + j0 + jj] = acc[bb][jj];
}

__global__ void fc1_reduce(const float* __restrict__ part, const float* __restrict__ bias,
                           float* __restrict__ h1)
{
    int idx = blockIdx.x * blockDim.x + threadIdx.x;
    if (idx >= 32 * 512) return;
    int jl = idx & 127;
    int jg = (idx >> 7) & 3;
    int b  = idx >> 9;
    int j = jg * 128 + jl;
    if (j >= 500) return;
    float s = bias[j];
    for (int ks = 0; ks < NSPLIT; ks++)
        s += part[((size_t)(jg * NSPLIT + ks) * 32 + b) * 128 + jl];
    h1[b * 500 + j] = s;    // pre-relu; relu applied when FC2 loads
}

// ---------------- small FC layers ----------------
__global__ void fc_small(const float* __restrict__ in, const float* __restrict__ w,
                         const float* __restrict__ bias, float* __restrict__ out,
                         int N, int K, int reluIn, int reluOut)
{
    int idx = blockIdx.x * blockDim.x + threadIdx.x;
    if (idx >= 32 * N) return;
    int b = idx / N, n = idx % N;
    float s = bias[n];
    const float* ip = in + b * K;
    const float* wp = w + n * K;
    for (int k = 0; k < K; k++) {
        float a = ip[k];
        if (reluIn) a = fmaxf(a, 0.f);
        s = fmaf(a, wp[k], s);
    }
    if (reluOut) s = fmaxf(s, 0.f);
    out[idx] = s;
}

// ---------------- host launcher ----------------
extern "C" void kernel_launch(void* const* d_in, const int* in_sizes, int n_in,
                              void* d_out, int out_size)
{
    const float* x     = (const float*)d_in[0];
    const float* w_in  = (const float*)d_in[1];
    const float* b_in  = (const float*)d_in[2];
    const float* w1    = (const float*)d_in[3];
    const float* b1    = (const float*)d_in[4];
    const float* w2    = (const float*)d_in[5];
    const float* b2    = (const float*)d_in[6];
    const float* w3    = (const float*)d_in[7];
    const float* b3    = (const float*)d_in[8];
    const float* w4    = (const float*)d_in[9];
    const float* b4    = (const float*)d_in[10];
    const float* w5    = (const float*)d_in[11];
    const float* b5    = (const float*)d_in[12];
    const float* wfc1  = (const float*)d_in[13];
    const float* bfc1  = (const float*)d_in[14];
    const float* wfc2  = (const float*)d_in[15];
    const float* bfc2  = (const float*)d_in[16];
    const float* wfc3  = (const float*)d_in[17];
    const float* bfc3  = (const float*)d_in[18];
    const float* wfc4  = (const float*)d_in[19];
    const float* bfc4  = (const float*)d_in[20];
    float* out = (float*)d_out;

    float *x1, *x2, *x3, *x4, *x5, *x6;
    float *wpin, *wf1, *wf2, *wf3, *wf4, *wf5;
    float *part, *h1, *h2, *h3, *phi, *trig;
    cudaGetSymbolAddress((void**)&x1, g_x1);
    cudaGetSymbolAddress((void**)&x2, g_x2);
    cudaGetSymbolAddress((void**)&x3, g_x3);
    cudaGetSymbolAddress((void**)&x4, g_x4);
    cudaGetSymbolAddress((void**)&x5, g_x5);
    cudaGetSymbolAddress((void**)&x6, g_x6);
    cudaGetSymbolAddress((void**)&wpin, g_wt_in);
    cudaGetSymbolAddress((void**)&wf1, g_wf1);
    cudaGetSymbolAddress((void**)&wf2, g_wf2);
    cudaGetSymbolAddress((void**)&wf3, g_wf3);
    cudaGetSymbolAddress((void**)&wf4, g_wf4);
    cudaGetSymbolAddress((void**)&wf5, g_wf5);
    cudaGetSymbolAddress((void**)&part, g_part);
    cudaGetSymbolAddress((void**)&h1, g_h1);
    cudaGetSymbolAddress((void**)&h2, g_h2);
    cudaGetSymbolAddress((void**)&h3, g_h3);
    cudaGetSymbolAddress((void**)&phi, g_phi);
    cudaGetSymbolAddress((void**)&trig, g_trig);

    const int smem_in = (1 * 8 * 36 + 1 * 25 * 32) * 8;       //  8704
    const int smem_c  = 26880 * 4;                            // 107520 -> 2 CTAs/SM
    cudaFuncSetAttribute(conv_mma<64>,
                         cudaFuncAttributeMaxDynamicSharedMemorySize, smem_c);
    cudaFuncSetAttribute(conv_mma<128>,
                         cudaFuncAttributeMaxDynamicSharedMemorySize, smem_c);

    // prologue
    init_tables<<<1, 1>>>(phi, trig);
    pack_w<<<(1 * 25 * 32 + 255) / 256, 256>>>(w_in, (float2*)wpin, 64, 1);
    pack_frag<<<(819200 + 255) / 256, 256>>>(w1, w2, w3, w4, w5,
                                             wf1, wf2, wf3, wf4, wf5);

    // conv_in (fp32, tiny)
    conv5x5_p<1, 32, 4, 1><<<dim3(6, 6, B), 128, smem_in>>>(x, (float2*)wpin, b_in, x1, 64);

    // tensor-core convs (3xTF32); concat fused via dual-write
    dim3 gm(2, 21, B);          // (xhalf, y, batch)
    conv_mma<64><<<gm, 256, smem_c>>>(x1, wf1, wf1 + 102400, b1, x2, 64, 0,
                                      x6, 192, 128);   // x2 also -> x6[128:192]
    conv_mma<64><<<gm, 256, smem_c>>>(x2, wf2, wf2 + 102400, b2, x3, 64, 0,
                                      x5, 128, 64);    // x3 also -> x5[64:128]
    conv_mma<64><<<gm, 256, smem_c>>>(x3, wf3, wf3 + 102400, b3, x4, 64, 0,
                                      nullptr, 0, 0);
    conv_mma<64><<<gm, 256, smem_c>>>(x4, wf4, wf4 + 102400, b4, x5, 128, 0,
                                      nullptr, 0, 0);  // x5[0:64]
    conv_mma<128><<<dim3(4, 21, B), 256, smem_c>>>(x5, wf5, wf5 + 409600, b5, x6, 192, 0,
                                                   nullptr, 0, 0);  // x6[0:128]

    // residual filters (closed-form projections; no FFT)
    filter_lat<<<(B * 192 * W + 255) / 256, 256>>>(x6, phi);
    filter_lon<<<(B * 192 * H * 32 + 255) / 256, 256>>>(x6, trig);

    // FC stack
    fc1_partial<<<dim3(NSPLIT, 4), 128>>>(x6, wfc1, part);
    fc1_reduce<<<64, 256>>>(part, bfc1, h1);
    fc_small<<<(32 * 200 + 255) / 256, 256>>>(h1, wfc2, bfc2, h2, 200, 500, 1, 1);
    fc_small<<<(32 * 50 + 255) / 256, 256>>>(h2, wfc3, bfc3, h3, 50, 200, 0, 1);
    fc_small<<<1, 64>>>(h3, wfc4, bfc4, out, 2, 50, 0, 0);
}

// round 8
// speedup vs baseline: 1.7589x; 1.4642x over previous
#include <cuda_runtime.h>
#include <cuda_bf16.h>
#include <math.h>
#include <stdint.h>

// ---------------- constants ----------------
#define B       32
#define H       21
#define W       180
#define PIX     (H*W)              // 3780
#define FEAT    (192*PIX)          // 725760
#define NS2     180
#define KC2     (FEAT/NS2)         // 4032
#define DPI     3.14159265358979323846

// ---------------- scratch (device globals; no runtime allocation) ----------------
__device__ float g_x1[B*64*PIX];
__device__ float g_x2[B*64*PIX];
__device__ float g_x3[B*64*PIX];
__device__ float g_x4[B*64*PIX];
__device__ float g_x5[B*128*PIX];
__device__ float g_x6[B*192*PIX];
__device__ float g_wt_in[64*1*25];        // conv_in packed float2 (oc pairs)
__device__ uint32_t g_wfrag[819200];      // bf16x2 A-frags: L1..L4 (102400 each), L5 (409600)
__device__ float g_part[4*NS2*4096];
__device__ float g_h1[B*500];
__device__ float g_h2[B*200];
__device__ float g_h3[B*50];
__device__ float g_phi[64];    // phi[3][21] + phi[63]=dy
__device__ float g_trig[720];  // c1,s1,c2,s2 each [180]

// ---------------- helpers ----------------
__device__ __forceinline__ uint32_t tf32u(float x) {
    uint32_t u;
    asm("cvt.rna.tf32.f32 %0, %1;" : "=r"(u) : "f"(x));
    return u;
}

__device__ __forceinline__ void mma_tf32(float* c, const uint32_t* a, const uint32_t* b) {
    asm("mma.sync.aligned.m16n8k8.row.col.f32.tf32.tf32.f32 "
        "{%0,%1,%2,%3},{%4,%5,%6,%7},{%8,%9},{%0,%1,%2,%3};"
        : "+f"(c[0]), "+f"(c[1]), "+f"(c[2]), "+f"(c[3])
        : "r"(a[0]), "r"(a[1]), "r"(a[2]), "r"(a[3]), "r"(b[0]), "r"(b[1]));
}

__device__ __forceinline__ void mma_bf16(float* c, const uint32_t* a, const uint32_t* b) {
    asm("mma.sync.aligned.m16n8k16.row.col.f32.bf16.bf16.f32 "
        "{%0,%1,%2,%3},{%4,%5,%6,%7},{%8,%9},{%0,%1,%2,%3};"
        : "+f"(c[0]), "+f"(c[1]), "+f"(c[2]), "+f"(c[3])
        : "r"(a[0]), "r"(a[1]), "r"(a[2]), "r"(a[3]), "r"(b[0]), "r"(b[1]));
}

__device__ __forceinline__ void bf16split(float v, uint16_t& h, uint16_t& l) {
    __nv_bfloat16 hb = __float2bfloat16(v);
    float hf = __bfloat162float(hb);
    __nv_bfloat16 lb = __float2bfloat16(v - hf);
    h = __bfloat16_as_ushort(hb);
    l = __bfloat16_as_ushort(lb);
}

// ---------------- init tables ----------------
__global__ void init_tables(float* phi, float* trig) {
    if (blockIdx.x == 0 && threadIdx.x == 0) {
        double beta = 2.28e-11;
        double L = sqrt(51.0 / beta);
        double spi = sqrt(DPI);
        double n0 = sqrt(spi), n1 = sqrt(2.0 * spi), n2 = sqrt(8.0 * spi);
        for (int i = 0; i < 21; i++) {
            double lat = 20.0 - 2.0 * i;
            double y = lat * 110000.0 / L;
            double e = exp(-y * y / 2.0);
            phi[i]      = (float)(e / n0);
            phi[21 + i] = (float)(e * 2.0 * y / n1);
            phi[42 + i] = (float)(e * (4.0 * y * y - 2.0) / n2);
        }
        phi[63] = (float)(2.0 * 110000.0 / L);
        for (int n = 0; n < 180; n++) {
            double t = 2.0 * DPI * (double)n / 180.0;
            trig[n]       = (float)cos(t);
            trig[180 + n] = (float)sin(t);
            trig[360 + n] = (float)cos(2.0 * t);
            trig[540 + n] = (float)sin(2.0 * t);
        }
    }
}

// ---------------- conv_in weight pack: [64][1][25] -> float2 pairs ---------------
__global__ void pack_w(const float* __restrict__ w, float2* __restrict__ wP,
                       int OC, int IC) {
    int OCP = OC >> 1;
    int idx = blockIdx.x * blockDim.x + threadIdx.x;
    int tot = IC * 25 * OCP;
    if (idx >= tot) return;
    int p  = idx % OCP;
    int k  = (idx / OCP) % 25;
    int ic = idx / (OCP * 25);
    float2 v;
    v.x = w[(2 * p    ) * IC * 25 + ic * 25 + k];
    v.y = w[(2 * p + 1) * IC * 25 + ic * 25 + k];
    wP[(ic * 25 + k) * OCP + p] = v;
}

// ---------------- bf16 A-frag pack for m16n8k16 ----------------------------------
// Per layer: hi[kpos 25][chunk IC/16][mtile 4][lane 32][reg 4] (bf16x2), lo at +WSZ.
// reg mapping: row = (ln>>2)+(reg&1)*8; k0 = 2*(ln&3)+(reg>>1)*8; elems (k0,k0+1).
__global__ void pack_frag(const float* __restrict__ w1, const float* __restrict__ w2,
                          const float* __restrict__ w3, const float* __restrict__ w4,
                          const float* __restrict__ w5, uint32_t* __restrict__ frag)
{
    int idx = blockIdx.x * blockDim.x + threadIdx.x;
    if (idx >= 409600) return;
    const float* w; int IC, t, mh = 0, base, WSZ;
    if (idx < 204800) {
        int l = idx / 51200; t = idx % 51200;
        w = l == 0 ? w1 : l == 1 ? w2 : l == 2 ? w3 : w4;
        IC = 64; base = l * 102400; WSZ = 51200;
    } else {
        int q = idx - 204800;
        mh = q / 102400; t = q % 102400;
        w = w5; IC = 128; base = 409600 + mh * 204800; WSZ = 102400;
    }
    int CH = IC / 16, P = CH * 512;
    int kpos = t / P; int r = t % P;
    int ck = r / 512; int r2 = r % 512;
    int mtile = r2 >> 7; int ln = (r2 >> 2) & 31; int reg = r2 & 3;
    int row = (ln >> 2) + (reg & 1) * 8;
    int k0  = 2 * (ln & 3) + (reg >> 1) * 8;
    int oc = mh * 64 + mtile * 16 + row;
    int ic = ck * 16 + k0;
    float v0 = w[((size_t)oc * IC + ic) * 25 + kpos];
    float v1 = w[((size_t)oc * IC + ic + 1) * 25 + kpos];
    uint16_t h0, l0, h1, l1;
    bf16split(v0, h0, l0);
    bf16split(v1, h1, l1);
    frag[base + t]       = (uint32_t)h0 | ((uint32_t)h1 << 16);
    frag[base + WSZ + t] = (uint32_t)l0 | ((uint32_t)l1 << 16);
}

// ---------------- conv_in: 1->64 fp32 direct (tiny) ------------------------------
#define FFMA2(d, a, b, c) \
    asm("fma.rn.f32x2 %0, %1, %2, %3;" : "=l"(d) : "l"(a), "l"(b), "l"(c))

template<int IC, int OCP, int YR, int ICC>
__global__ __launch_bounds__(OCP*YR, 3)
void conv5x5_p(const float* __restrict__ in, const float2* __restrict__ wP,
               const float* __restrict__ bias, float* __restrict__ out,
               int outCtot)
{
    constexpr int ROWS = YR + 4;
    constexpr int BT = OCP * YR;
    constexpr int XT = 30;
    extern __shared__ char smraw[];
    float2* sIn = (float2*)smraw;
    float2* sW  = sIn + ICC * ROWS * 36;

    int tid = threadIdx.x;
    int ocp = tid % OCP;
    int yl = tid / OCP;
    int x0 = blockIdx.x * XT, y0 = blockIdx.y * YR, b = blockIdx.z;
    int y = y0 + yl;
    bool valid = (y < H);

    unsigned long long acc[XT];
#pragma unroll
    for (int j = 0; j < XT; j++) acc[j] = 0ull;

#pragma unroll 1
    for (int ic0 = 0; ic0 < IC; ic0 += ICC) {
        __syncthreads();
        for (int i = tid; i < ICC * ROWS * 36; i += BT) {
            int ic = i / (ROWS * 36);
            int r  = (i / 36) % ROWS;
            int xx = i % 36;
            int gy = y0 - 2 + r;
            int gx = x0 - 2 + xx;
            float v = 0.f;
            if (gy >= 0 && gy < H && gx >= 0 && gx < W)
                v = in[((b * IC + ic0 + ic) * H + gy) * W + gx];
            sIn[i] = make_float2(v, v);
        }
        for (int i = tid; i < ICC * 25 * OCP; i += BT)
            sW[i] = wP[ic0 * 25 * OCP + i];
        __syncthreads();

        if (valid) {
#pragma unroll 1
            for (int ic = 0; ic < ICC; ic++) {
#pragma unroll
                for (int kh = 0; kh < 5; kh++) {
                    unsigned long long wp[5];
#pragma unroll
                    for (int kw = 0; kw < 5; kw++)
                        wp[kw] = *reinterpret_cast<const unsigned long long*>(
                            &sW[(ic * 25 + kh * 5 + kw) * OCP + ocp]);
                    const float2* row = &sIn[(ic * ROWS + yl + kh) * 36];
#pragma unroll
                    for (int xs3 = 0; xs3 < 3; xs3++) {
                        const int xs = xs3 * 10;
                        unsigned long long winp[14];
#pragma unroll
                        for (int t = 0; t < 14; t++)
                            winp[t] = *reinterpret_cast<const unsigned long long*>(&row[xs + t]);
#pragma unroll
                        for (int kw = 0; kw < 5; kw++) {
#pragma unroll
                            for (int j = 0; j < 10; j++)
                                FFMA2(acc[xs + j], wp[kw], winp[j + kw], acc[xs + j]);
                        }
                    }
                }
            }
        }
    }

    if (valid) {
        int oc0 = 2 * ocp;
        float bv0 = bias[oc0], bv1 = bias[oc0 + 1];
        float* o0 = out + ((size_t)(b * outCtot + oc0) * H + y) * W + x0;
        float* o1 = o0 + (size_t)H * W;
#pragma unroll
        for (int j = 0; j < XT; j += 2) {
            float2 va = *reinterpret_cast<float2*>(&acc[j]);
            float2 vb = *reinterpret_cast<float2*>(&acc[j + 1]);
            *reinterpret_cast<float2*>(o0 + j) =
                make_float2(fmaxf(va.x + bv0, 0.f), fmaxf(vb.x + bv0, 0.f));
            *reinterpret_cast<float2*>(o1 + j) =
                make_float2(fmaxf(va.y + bv1, 0.f), fmaxf(vb.y + bv1, 0.f));
        }
    }
}

// ---------------- tensor conv: 3-term bf16 split, m16n8k16 -----------------------
// Tile M=64 oc x N=96 px per CTA; K = IC*25 via 16-ic chunks (one K16 mma per tap).
// Input smem as bf16x2 (even/odd ic pairs) = B-frag register pairing; pair-stride
// 520 == 8 mod 32 -> conflict-free B loads. Weights staged in A-frag order.
template<int IC>
__global__ __launch_bounds__(256, 3)
void conv_mma(const float* __restrict__ in, const uint32_t* __restrict__ wfrag,
              const float* __restrict__ bias,
              float* __restrict__ out, int outCtot,
              float* __restrict__ out2, int out2Ctot, int out2Off)
{
    constexpr int CH = IC / 16;
    constexpr int WSZ = 25 * CH * 512;
    constexpr int XS = 520, RS = 104;
    extern __shared__ uint32_t smu[];
    uint32_t* sInH = smu;             // 4160
    uint32_t* sInL = smu + 4160;      // 4160
    uint32_t* sWh  = smu + 8320;      // 2560
    uint32_t* sWl  = smu + 10880;     // 2560 (total 13440 u32 = 53760 B)

    int tid = threadIdx.x, lane = tid & 31, warpId = tid >> 5;
    int wm = warpId >> 2, wn = warpId & 3;
    int xh = blockIdx.x & 1, mh = blockIdx.x >> 1;
    int y = blockIdx.y, b = blockIdx.z;
    int x0 = xh * 96;
    const uint32_t* wH = wfrag + mh * 2 * WSZ;
    const uint32_t* wL = wH + WSZ;

    float c[2][3][4] = {};
    int p = warpId;                   // icpair 0..7 for the loader role

#pragma unroll 1
    for (int ch = 0; ch < CH; ch++) {
        __syncthreads();
        {   // input tile: 8 icpairs x 5 rows x 104, split+packed bf16x2
            const float* in0 = in + (size_t)(b * IC + ch * 16 + 2 * p) * PIX;
            const float* in1 = in0 + PIX;
            uint32_t* dH = sInH + p * XS;
            uint32_t* dL = sInL + p * XS;
#pragma unroll
            for (int r = 0; r < 5; r++) {
                int gy = y + r - 2;
                bool okY = (gy >= 0 && gy < H);
#pragma unroll
                for (int xx = lane; xx < RS; xx += 32) {
                    int gx = x0 - 2 + xx;
                    float v0 = 0.f, v1 = 0.f;
                    if (okY && gx >= 0 && gx < W) {
                        v0 = in0[gy * W + gx];
                        v1 = in1[gy * W + gx];
                    }
                    uint16_t h0, l0, h1, l1;
                    bf16split(v0, h0, l0);
                    bf16split(v1, h1, l1);
                    dH[r * RS + xx] = (uint32_t)h0 | ((uint32_t)h1 << 16);
                    dL[r * RS + xx] = (uint32_t)l0 | ((uint32_t)l1 << 16);
                }
            }
        }
#pragma unroll 1
        for (int kh = 0; kh < 5; kh++) {
            __syncthreads();
            for (int i = tid; i < 2560; i += 256) {
                int kw = i >> 9, off = i & 511;
                int src = ((kh * 5 + kw) * CH + ch) * 512 + off;
                sWh[i] = wH[src];
                sWl[i] = wL[src];
            }
            __syncthreads();
#pragma unroll
            for (int kw = 0; kw < 5; kw++) {
                uint32_t ah[2][4], al[2][4];
#pragma unroll
                for (int mt = 0; mt < 2; mt++) {
                    int base = (kw * 4 + wm * 2 + mt) * 128 + lane * 4;
                    *(uint4*)ah[mt] = *(const uint4*)&sWh[base];
                    *(uint4*)al[mt] = *(const uint4*)&sWl[base];
                }
                int bbase = (lane & 3) * XS + kh * RS + wn * 24 + (lane >> 2) + kw;
#pragma unroll
                for (int nt = 0; nt < 3; nt++) {
                    uint32_t bh[2], bl[2];
                    int bi = bbase + nt * 8;
                    bh[0] = sInH[bi]; bh[1] = sInH[bi + 4 * XS];
                    bl[0] = sInL[bi]; bl[1] = sInL[bi + 4 * XS];
#pragma unroll
                    for (int mt = 0; mt < 2; mt++) {
                        mma_bf16(c[mt][nt], ah[mt], bh);
                        mma_bf16(c[mt][nt], ah[mt], bl);
                        mma_bf16(c[mt][nt], al[mt], bh);
                    }
                }
            }
        }
    }

    // epilogue: bias + relu + store, optional concat dual-write
    int ocL = mh * 64 + wm * 32;
#pragma unroll
    for (int mt = 0; mt < 2; mt++) {
        int ocRow = ocL + mt * 16 + (lane >> 2);
        float bv0 = bias[ocRow], bv8 = bias[ocRow + 8];
#pragma unroll
        for (int nt = 0; nt < 3; nt++) {
            int x = x0 + wn * 24 + nt * 8 + (lane & 3) * 2;
            if (x < W) {
                float2 v0 = make_float2(fmaxf(c[mt][nt][0] + bv0, 0.f),
                                        fmaxf(c[mt][nt][1] + bv0, 0.f));
                float2 v1 = make_float2(fmaxf(c[mt][nt][2] + bv8, 0.f),
                                        fmaxf(c[mt][nt][3] + bv8, 0.f));
                size_t o0 = ((size_t)(b * outCtot + ocRow) * H + y) * W + x;
                size_t o1 = o0 + (size_t)8 * H * W;
                *(float2*)&out[o0] = v0;
                *(float2*)&out[o1] = v1;
                if (out2) {
                    size_t q0 = ((size_t)(b * out2Ctot + out2Off + ocRow) * H + y) * W + x;
                    size_t q1 = q0 + (size_t)8 * H * W;
                    *(float2*)&out2[q0] = v0;
                    *(float2*)&out2[q1] = v1;
                }
            }
        }
    }
}

// ---------------- Hermite residual along lat, in place ---------------------------
__global__ void filter_lat(float* __restrict__ x, const float* __restrict__ phi)
{
    int idx = blockIdx.x * blockDim.x + threadIdx.x;
    if (idx >= B * 192 * W) return;
    int xi = idx % W;
    int c  = (idx / W) % 192;
    int b  = idx / (W * 192);
    float* base = x + (size_t)((b * 192 + c) * H) * W + xi;
    float v[21];
#pragma unroll
    for (int y = 0; y < 21; y++) v[y] = base[y * W];
    float dy = phi[63];
    float u0 = 0.f, u1 = 0.f, u2 = 0.f;
#pragma unroll
    for (int y = 0; y < 21; y++) {
        u0 += v[y] * phi[y];
        u1 += v[y] * phi[21 + y];
        u2 += v[y] * phi[42 + y];
    }
    u0 *= dy; u1 *= dy; u2 *= dy;
#pragma unroll
    for (int y = 0; y < 21; y++)
        base[y * W] = v[y] - (u0 * phi[y] + u1 * phi[21 + y] + u2 * phi[42 + y]);
}

// ---------------- Fourier low-mode residual along lon (k=0,1,2), in place --------
__global__ void filter_lon(float* __restrict__ x, const float* __restrict__ trig)
{
    int gw = (blockIdx.x * blockDim.x + threadIdx.x) >> 5;
    int lane = threadIdx.x & 31;
    if (gw >= B * 192 * H) return;
    float* row = x + (size_t)gw * W;
    const float* c1 = trig, *s1 = trig + 180, *c2 = trig + 360, *s2 = trig + 540;
    float v[6];
    float q0 = 0.f, q1 = 0.f, q2 = 0.f, q3 = 0.f, q4 = 0.f;
#pragma unroll
    for (int t = 0; t < 6; t++) {
        int n = t * 32 + lane;
        if (n < W) {
            float xv = row[n];
            v[t] = xv;
            q0 += xv;
            q1 += xv * c1[n];
            q2 += xv * s1[n];
            q3 += xv * c2[n];
            q4 += xv * s2[n];
        }
    }
#pragma unroll
    for (int o = 16; o; o >>= 1) {
        q0 += __shfl_xor_sync(0xffffffffu, q0, o);
        q1 += __shfl_xor_sync(0xffffffffu, q1, o);
        q2 += __shfl_xor_sync(0xffffffffu, q2, o);
        q3 += __shfl_xor_sync(0xffffffffu, q3, o);
        q4 += __shfl_xor_sync(0xffffffffu, q4, o);
    }
    const float inv = 1.f / 180.f, inv2 = 2.f / 180.f;
#pragma unroll
    for (int t = 0; t < 6; t++) {
        int n = t * 32 + lane;
        if (n < W)
            row[n] = v[t] - q0 * inv
                   - inv2 * (q1 * c1[n] + q2 * s1[n] + q3 * c2[n] + q4 * s2[n]);
    }
}

// ---------------- FC1 via tf32 mma: out[512 j][32 b], split-K=180 ----------------
// 8 warps = 8 mtiles of 16 j; frags loaded straight from gmem (L1/L2 cached).
__global__ __launch_bounds__(256)
void fc1_mma(const float* __restrict__ act, const float* __restrict__ w,
             float* __restrict__ part)
{
    int tid = threadIdx.x, lane = tid & 31, wid = tid >> 5;
    int ks = blockIdx.x, jg = blockIdx.y;
    int r = lane >> 2, cc = lane & 3;
    int j0 = jg * 128 + wid * 16 + r;
    int j1 = j0 + 8;
    bool ok0 = j0 < 500, ok1 = j1 < 500;
    const float* w0 = w + (size_t)j0 * FEAT;
    const float* w1 = w + (size_t)j1 * FEAT;
    const float* a0 = act + (size_t)(0 * 8 + r) * FEAT;
    const float* a1 = act + (size_t)(1 * 8 + r) * FEAT;
    const float* a2 = act + (size_t)(2 * 8 + r) * FEAT;
    const float* a3 = act + (size_t)(3 * 8 + r) * FEAT;
    int kb = ks * KC2;
    float acc[4][4] = {};

#pragma unroll 2
    for (int k = kb; k < kb + KC2; k += 8) {
        uint32_t a[4];
        a[0] = ok0 ? tf32u(w0[k + cc])     : 0u;
        a[1] = ok1 ? tf32u(w1[k + cc])     : 0u;
        a[2] = ok0 ? tf32u(w0[k + 4 + cc]) : 0u;
        a[3] = ok1 ? tf32u(w1[k + 4 + cc]) : 0u;
        uint32_t bb[2];
        bb[0] = tf32u(a0[k + cc]); bb[1] = tf32u(a0[k + 4 + cc]);
        mma_tf32(acc[0], a, bb);
        bb[0] = tf32u(a1[k + cc]); bb[1] = tf32u(a1[k + 4 + cc]);
        mma_tf32(acc[1], a, bb);
        bb[0] = tf32u(a2[k + cc]); bb[1] = tf32u(a2[k + 4 + cc]);
        mma_tf32(acc[2], a, bb);
        bb[0] = tf32u(a3[k + cc]); bb[1] = tf32u(a3[k + 4 + cc]);
        mma_tf32(acc[3], a, bb);
    }

    float* pp = part + (size_t)(jg * NS2 + ks) * 4096;
    int jr = wid * 16 + r;
#pragma unroll
    for (int nt = 0; nt < 4; nt++) {
        int bc = nt * 8 + 2 * cc;
        pp[jr * 32 + bc]           = acc[nt][0];
        pp[jr * 32 + bc + 1]       = acc[nt][1];
        pp[(jr + 8) * 32 + bc]     = acc[nt][2];
        pp[(jr + 8) * 32 + bc + 1] = acc[nt][3];
    }
}

__global__ void fc1_reduce(const float* __restrict__ part, const float* __restrict__ bias,
                           float* __restrict__ h1)
{
    int idx = blockIdx.x * blockDim.x + threadIdx.x;
    if (idx >= 32 * 512) return;
    int b = idx & 31;
    int j = idx >> 5;
    if (j >= 500) return;
    int jg = j >> 7, jr = j & 127;
    float s = bias[j];
    const float* pp = part + (size_t)jg * NS2 * 4096 + jr * 32 + b;
    for (int ksi = 0; ksi < NS2; ksi++) s += pp[(size_t)ksi * 4096];
    h1[b * 500 + j] = s;    // pre-relu; relu applied when FC2 loads
}

// ---------------- small FC layers ----------------
__global__ void fc_small(const float* __restrict__ in, const float* __restrict__ w,
                         const float* __restrict__ bias, float* __restrict__ out,
                         int N, int K, int reluIn, int reluOut)
{
    int idx = blockIdx.x * blockDim.x + threadIdx.x;
    if (idx >= 32 * N) return;
    int b = idx / N, n = idx % N;
    float s = bias[n];
    const float* ip = in + b * K;
    const float* wp = w + n * K;
    for (int k = 0; k < K; k++) {
        float a = ip[k];
        if (reluIn) a = fmaxf(a, 0.f);
        s = fmaf(a, wp[k], s);
    }
    if (reluOut) s = fmaxf(s, 0.f);
    out[idx] = s;
}

// ---------------- host launcher ----------------
extern "C" void kernel_launch(void* const* d_in, const int* in_sizes, int n_in,
                              void* d_out, int out_size)
{
    const float* x     = (const float*)d_in[0];
    const float* w_in  = (const float*)d_in[1];
    const float* b_in  = (const float*)d_in[2];
    const float* w1    = (const float*)d_in[3];
    const float* b1    = (const float*)d_in[4];
    const float* w2    = (const float*)d_in[5];
    const float* b2    = (const float*)d_in[6];
    const float* w3    = (const float*)d_in[7];
    const float* b3    = (const float*)d_in[8];
    const float* w4    = (const float*)d_in[9];
    const float* b4    = (const float*)d_in[10];
    const float* w5    = (const float*)d_in[11];
    const float* b5    = (const float*)d_in[12];
    const float* wfc1  = (const float*)d_in[13];
    const float* bfc1  = (const float*)d_in[14];
    const float* wfc2  = (const float*)d_in[15];
    const float* bfc2  = (const float*)d_in[16];
    const float* wfc3  = (const float*)d_in[17];
    const float* bfc3  = (const float*)d_in[18];
    const float* wfc4  = (const float*)d_in[19];
    const float* bfc4  = (const float*)d_in[20];
    float* out = (float*)d_out;

    float *x1, *x2, *x3, *x4, *x5, *x6;
    float *wpin, *part, *h1, *h2, *h3, *phi, *trig;
    uint32_t* wfrag;
    cudaGetSymbolAddress((void**)&x1, g_x1);
    cudaGetSymbolAddress((void**)&x2, g_x2);
    cudaGetSymbolAddress((void**)&x3, g_x3);
    cudaGetSymbolAddress((void**)&x4, g_x4);
    cudaGetSymbolAddress((void**)&x5, g_x5);
    cudaGetSymbolAddress((void**)&x6, g_x6);
    cudaGetSymbolAddress((void**)&wpin, g_wt_in);
    cudaGetSymbolAddress((void**)&wfrag, g_wfrag);
    cudaGetSymbolAddress((void**)&part, g_part);
    cudaGetSymbolAddress((void**)&h1, g_h1);
    cudaGetSymbolAddress((void**)&h2, g_h2);
    cudaGetSymbolAddress((void**)&h3, g_h3);
    cudaGetSymbolAddress((void**)&phi, g_phi);
    cudaGetSymbolAddress((void**)&trig, g_trig);

    const int smem_in = (1 * 8 * 36 + 1 * 25 * 32) * 8;   //  8704
    const int smem_c  = 13440 * 4;                        // 53760 -> 3 CTAs/SM
    cudaFuncSetAttribute(conv_mma<64>,
                         cudaFuncAttributeMaxDynamicSharedMemorySize, smem_c);
    cudaFuncSetAttribute(conv_mma<128>,
                         cudaFuncAttributeMaxDynamicSharedMemorySize, smem_c);

    // prologue
    init_tables<<<1, 1>>>(phi, trig);
    pack_w<<<(1 * 25 * 32 + 255) / 256, 256>>>(w_in, (float2*)wpin, 64, 1);
    pack_frag<<<1600, 256>>>(w1, w2, w3, w4, w5, wfrag);

    // conv_in (fp32, tiny)
    conv5x5_p<1, 32, 4, 1><<<dim3(6, 6, B), 128, smem_in>>>(x, (float2*)wpin, b_in, x1, 64);

    // tensor-core convs (3-term bf16 split); concat fused via dual-write
    dim3 gm(2, 21, B);          // (xhalf, y, batch)
    conv_mma<64><<<gm, 256, smem_c>>>(x1, wfrag,            b1, x2, 64,
                                      x6, 192, 128);   // x2 also -> x6[128:192]
    conv_mma<64><<<gm, 256, smem_c>>>(x2, wfrag + 102400,   b2, x3, 64,
                                      x5, 128, 64);    // x3 also -> x5[64:128]
    conv_mma<64><<<gm, 256, smem_c>>>(x3, wfrag + 204800,   b3, x4, 64,
                                      nullptr, 0, 0);
    conv_mma<64><<<gm, 256, smem_c>>>(x4, wfrag + 307200,   b4, x5, 128,
                                      nullptr, 0, 0);  // x5[0:64]
    conv_mma<128><<<dim3(4, 21, B), 256, smem_c>>>(x5, wfrag + 409600, b5, x6, 192,
                                                   nullptr, 0, 0);  // x6[0:128]

    // residual filters (closed-form projections; no FFT)
    filter_lat<<<(B * 192 * W + 255) / 256, 256>>>(x6, phi);
    filter_lon<<<(B * 192 * H * 32 + 255) / 256, 256>>>(x6, trig);

    // FC stack
    fc1_mma<<<dim3(NS2, 4), 256>>>(x6, wfc1, part);
    fc1_reduce<<<64, 256>>>(part, bfc1, h1);
    fc_small<<<(32 * 200 + 255) / 256, 256>>>(h1, wfc2, bfc2, h2, 200, 500, 1, 1);
    fc_small<<<(32 * 50 + 255) / 256, 256>>>(h2, wfc3, bfc3, h3, 50, 200, 0, 1);
    fc_small<<<1, 64>>>(h3, wfc4, bfc4, out, 2, 50, 0, 0);
}